// round 15
// baseline (speedup 1.0000x reference)
#include <cuda_runtime.h>
#include <cstdint>
#include <math_constants.h>

#define NMAX 100000
#define EMAX 3200000
#define CH 64
#define KTOP 30
#define PLEN 1950   // 30 * 65
#define SEGMAX 4096
#define SCAN_B 1024
#define NBLK 128    // >= ceil(NMAX/SCAN_B) = 98

#define FMA_F32X2(d, a, b, c) \
    asm("fma.rn.f32x2 %0, %1, %2, %3;" : "=l"(d) : "l"(a), "l"(b), "l"(c))
#define PACK_DUP_F32X2(d, a) \
    asm("mov.b64 %0, {%1, %1};" : "=l"(d) : "f"(a))
#define UNPACK_F32X2(lo, hi, in) \
    asm("mov.b64 {%0, %1}, %2;" : "=f"(lo), "=f"(hi) : "l"(in))

// ---------------- scratch (static device globals; no allocs allowed) -------
__device__ float g_y[NMAX * CH];     // (x @ W1) * dis[row]
__device__ float g_x1[NMAX * CH];
__device__ float g_z[NMAX];          // (x1 @ W2) * dis[row]
__device__ int   g_indeg[NMAX];
__device__ int   g_lpre[NMAX];       // exclusive prefix within scan block
__device__ int   g_bsum[NBLK];
__device__ int   g_estart[NMAX + 1];
__device__ int   g_cursor[NMAX];
__device__ int   g_srow[EMAX];       // edge sources grouped by destination

// ---------------- K0: zero g_indeg -----------------------------------------
__global__ void zero_kernel(int n4) {
    int i = blockIdx.x * blockDim.x + threadIdx.x;
    if (i < n4) ((int4*)g_indeg)[i] = make_int4(0, 0, 0, 0);
}

// ---------------- K1: in-degree counts (8-edge batched, int) ----------------
__global__ void deg_kernel(const int* __restrict__ row,
                           const int* __restrict__ col, int E) {
    int g = blockIdx.x * blockDim.x + threadIdx.x;
    int e0 = g * 8;
    if (e0 >= E) return;
    int rr[8], cc[8];
    if (e0 + 7 < E) {
        int4 r0 = __ldg((const int4*)row + g * 2);
        int4 r1 = __ldg((const int4*)row + g * 2 + 1);
        int4 c0 = __ldg((const int4*)col + g * 2);
        int4 c1 = __ldg((const int4*)col + g * 2 + 1);
        rr[0]=r0.x; rr[1]=r0.y; rr[2]=r0.z; rr[3]=r0.w;
        rr[4]=r1.x; rr[5]=r1.y; rr[6]=r1.z; rr[7]=r1.w;
        cc[0]=c0.x; cc[1]=c0.y; cc[2]=c0.z; cc[3]=c0.w;
        cc[4]=c1.x; cc[5]=c1.y; cc[6]=c1.z; cc[7]=c1.w;
    } else {
#pragma unroll
        for (int k = 0; k < 8; k++) {
            int e = e0 + k;
            rr[k] = (e < E) ? row[e] : 0;
            cc[k] = (e < E) ? col[e] : 0;
        }
    }
#pragma unroll
    for (int k = 0; k < 8; k++)
        if (rr[k] != cc[k]) atomicAdd(&g_indeg[cc[k]], 1);
}

// ---------------- K2a: per-block scan of indeg ------------------------------
__global__ void scanA_kernel(int n) {
    __shared__ int s[SCAN_B];
    int b = blockIdx.x, t = threadIdx.x;
    int i = b * SCAN_B + t;
    int v = (i < n) ? g_indeg[i] : 0;
    s[t] = v;
    __syncthreads();
    for (int off = 1; off < SCAN_B; off <<= 1) {
        int u = (t >= off) ? s[t - off] : 0;
        __syncthreads();
        s[t] += u;
        __syncthreads();
    }
    if (i < n) g_lpre[i] = s[t] - v;
    if (t == SCAN_B - 1) g_bsum[b] = s[t];
}

// ---------------- K2c: scan block sums locally; apply -> estart, cursor -----
__global__ void scanC_kernel(int n, int nb) {
    __shared__ int bs[NBLK];
    int t = threadIdx.x;
    if (t < NBLK) bs[t] = (t < nb) ? g_bsum[t] : 0;
    __syncthreads();
    for (int off = 1; off < NBLK; off <<= 1) {
        int u = (t >= off && t < NBLK) ? bs[t - off] : 0;
        __syncthreads();
        if (t < NBLK) bs[t] += u;   // inclusive scan of block sums
        __syncthreads();
    }
    int i = blockIdx.x * blockDim.x + t;
    if (i < n) {
        int b = i >> 10;
        int pre = b ? bs[b - 1] : 0;
        int v = g_lpre[i] + pre;
        g_estart[i] = v;
        g_cursor[i] = v;
    }
    if (blockIdx.x == 0 && t == 0)
        g_estart[n] = bs[nb - 1];   // total non-self edges
}

// ---------------- K3: y = (x @ W1) * rsqrt(indeg+1) -------------------------
#define GEMM_TR 128
#define XPITCH 132
#define GEMM_SMEM ((GEMM_TR * XPITCH + 128 * 64) * 4)

__global__ void gemm1_kernel(const float* __restrict__ x,
                             const float* __restrict__ W, int n) {
    extern __shared__ float smem[];
    float* xs = smem;                       // [128][132]
    float* ws = smem + GEMM_TR * XPITCH;    // [128][64]
    int t = threadIdx.x;
    int row0 = blockIdx.x * GEMM_TR;

    for (int i = t; i < 128 * 64 / 4; i += 256)
        ((float4*)ws)[i] = ((const float4*)W)[i];
    for (int i = t; i < GEMM_TR * 32; i += 256) {
        int r = i >> 5, c4 = i & 31;
        float4 v = make_float4(0.f, 0.f, 0.f, 0.f);
        if (row0 + r < n) v = ((const float4*)x)[(size_t)(row0 + r) * 32 + c4];
        *(float4*)&xs[r * XPITCH + c4 * 4] = v;
    }
    __syncthreads();

    int tx = t & 7;
    int ty = t >> 3;
    unsigned long long acc[4][4];
#pragma unroll
    for (int i = 0; i < 4; i++)
#pragma unroll
        for (int j = 0; j < 4; j++) acc[i][j] = 0ull;

#pragma unroll 4
    for (int k = 0; k < 128; k++) {
        const unsigned long long* w64 =
            (const unsigned long long*)(ws + k * 64 + tx * 8);
        unsigned long long b0 = w64[0], b1 = w64[1], b2 = w64[2], b3 = w64[3];
#pragma unroll
        for (int i = 0; i < 4; i++) {
            float a = xs[(ty * 4 + i) * XPITCH + k];
            unsigned long long ad;
            PACK_DUP_F32X2(ad, a);
            FMA_F32X2(acc[i][0], ad, b0, acc[i][0]);
            FMA_F32X2(acc[i][1], ad, b1, acc[i][1]);
            FMA_F32X2(acc[i][2], ad, b2, acc[i][2]);
            FMA_F32X2(acc[i][3], ad, b3, acc[i][3]);
        }
    }

#pragma unroll
    for (int i = 0; i < 4; i++) {
        int r = row0 + ty * 4 + i;
        if (r < n) {
            float d = rsqrtf((float)g_indeg[r] + 1.0f);
            float f[8];
#pragma unroll
            for (int j = 0; j < 4; j++)
                UNPACK_F32X2(f[2 * j], f[2 * j + 1], acc[i][j]);
            size_t ofs = (size_t)r * 64 + tx * 8;
            *(float4*)&g_y[ofs] =
                make_float4(f[0] * d, f[1] * d, f[2] * d, f[3] * d);
            *(float4*)&g_y[ofs + 4] =
                make_float4(f[4] * d, f[5] * d, f[6] * d, f[7] * d);
        }
    }
}

// ---------------- K4: scatter edges into dest-grouped list (8-batched) ------
__global__ void scatter_kernel(const int* __restrict__ row,
                               const int* __restrict__ col, int E) {
    int g = blockIdx.x * blockDim.x + threadIdx.x;
    int e0 = g * 8;
    if (e0 >= E) return;
    int rr[8], cc[8];
    if (e0 + 7 < E) {
        int4 r0 = __ldg((const int4*)row + g * 2);
        int4 r1 = __ldg((const int4*)row + g * 2 + 1);
        int4 c0 = __ldg((const int4*)col + g * 2);
        int4 c1 = __ldg((const int4*)col + g * 2 + 1);
        rr[0]=r0.x; rr[1]=r0.y; rr[2]=r0.z; rr[3]=r0.w;
        rr[4]=r1.x; rr[5]=r1.y; rr[6]=r1.z; rr[7]=r1.w;
        cc[0]=c0.x; cc[1]=c0.y; cc[2]=c0.z; cc[3]=c0.w;
        cc[4]=c1.x; cc[5]=c1.y; cc[6]=c1.z; cc[7]=c1.w;
    } else {
#pragma unroll
        for (int k = 0; k < 8; k++) {
            int e = e0 + k;
            rr[k] = (e < E) ? row[e] : 0;
            cc[k] = (e < E) ? col[e] : 0;
        }
    }
    int pos[8];
#pragma unroll
    for (int k = 0; k < 8; k++)
        if (rr[k] != cc[k]) pos[k] = atomicAdd(&g_cursor[cc[k]], 1);
#pragma unroll
    for (int k = 0; k < 8; k++)
        if (rr[k] != cc[k]) g_srow[pos[k]] = rr[k];
}

// ---------------- K5: gather conv1 + tanh + W2 dot (warp/node, unroll-4) ----
__global__ void gather1_kernel(const float* __restrict__ W2,
                               const float* __restrict__ b1, int n) {
    int c = (blockIdx.x * blockDim.x + threadIdx.x) >> 5;
    int lane = threadIdx.x & 31;
    if (c >= n) return;
    int s = __ldg(&g_estart[c]);
    int e = __ldg(&g_estart[c + 1]);

    size_t base = (size_t)c * 64 + lane * 2;
    float2 self = *(const float2*)&g_y[base];
    float2 a0 = make_float2(0.f, 0.f), a1 = a0, a2 = a0, a3 = a0;

    int i = s;
    for (; i + 4 <= e; i += 4) {
        int r0 = __ldg(&g_srow[i]);
        int r1 = __ldg(&g_srow[i + 1]);
        int r2 = __ldg(&g_srow[i + 2]);
        int r3 = __ldg(&g_srow[i + 3]);
        float2 v0 = *(const float2*)&g_y[(size_t)r0 * 64 + lane * 2];
        float2 v1 = *(const float2*)&g_y[(size_t)r1 * 64 + lane * 2];
        float2 v2 = *(const float2*)&g_y[(size_t)r2 * 64 + lane * 2];
        float2 v3 = *(const float2*)&g_y[(size_t)r3 * 64 + lane * 2];
        a0.x += v0.x; a0.y += v0.y;
        a1.x += v1.x; a1.y += v1.y;
        a2.x += v2.x; a2.y += v2.y;
        a3.x += v3.x; a3.y += v3.y;
    }
    for (; i < e; i++) {
        int r = __ldg(&g_srow[i]);
        float2 v = *(const float2*)&g_y[(size_t)r * 64 + lane * 2];
        a0.x += v.x; a0.y += v.y;
    }
    float accx = (a0.x + a1.x) + (a2.x + a3.x) + self.x;
    float accy = (a0.y + a1.y) + (a2.y + a3.y) + self.y;

    float dc = rsqrtf((float)g_indeg[c] + 1.0f);
    float2 bb = *(const float2*)&b1[lane * 2];
    float v0 = tanhf(accx * dc + bb.x);
    float v1 = tanhf(accy * dc + bb.y);
    *(float2*)&g_x1[base] = make_float2(v0, v1);

    float2 w2 = *(const float2*)&W2[lane * 2];
    float dot = v0 * w2.x + v1 * w2.y;
#pragma unroll
    for (int off = 16; off; off >>= 1) dot += __shfl_xor_sync(~0u, dot, off);
    if (lane == 0) g_z[c] = dot * dc;
}

// ---------------- K9: fused conv2-gather + x2 + sort-pool + CNN head --------
__device__ __forceinline__ int lower_bound_i(const int* __restrict__ b,
                                             int n, int v) {
    int lo = 0, hi = n;
    while (lo < hi) {
        int m = (lo + hi) >> 1;
        if (__ldg(b + m) < v) lo = m + 1; else hi = m;
    }
    return lo;
}

__global__ void head_kernel(const int* __restrict__ batch,
                            const float* __restrict__ b2,
                            const float* __restrict__ w3, const float* __restrict__ b3,
                            const float* __restrict__ w4, const float* __restrict__ b4,
                            const float* __restrict__ fw1, const float* __restrict__ fb1,
                            const float* __restrict__ fw2, const float* __restrict__ fb2,
                            float* __restrict__ out, int B, int n) {
    __shared__ float sc[SEGMAX];    // selection scores (destroyed)
    __shared__ float x2c[SEGMAX];   // preserved x2 copy
    __shared__ int sel[KTOP];
    __shared__ float p[PLEN];
    __shared__ float c3[320];
    __shared__ float pl[160];
    __shared__ float h[192];
    __shared__ float ll[128];
    __shared__ float o[18];
    __shared__ unsigned long long redw[8];

    int g = blockIdx.x;
    int t = threadIdx.x;
    int lane = t & 31;
    int warp = t >> 5;

    int start = lower_bound_i(batch, n, g);
    int end   = lower_bound_i(batch, n, g + 1);
    int cnt = min(end - start, SEGMAX);
    int ksel = min(cnt, KTOP);

    // fused gather2: x2[node] = tanh((sum_z + z[node]) * rsqrt(indeg+1) + b2)
    // warp-per-node; lane-strided sum identical to the old gather2_kernel.
    float b2v = b2[0];
    for (int i = warp; i < cnt; i += 8) {
        int c = start + i;
        int s = __ldg(&g_estart[c]);
        int e = __ldg(&g_estart[c + 1]);
        float sum = 0.f;
        for (int j = s + lane; j < e; j += 32) {
            int r = __ldg(&g_srow[j]);
            sum += __ldg(&g_z[r]);
        }
#pragma unroll
        for (int off = 16; off; off >>= 1)
            sum += __shfl_xor_sync(~0u, sum, off);
        if (lane == 0) {
            float dc = rsqrtf((float)__ldg(&g_indeg[c]) + 1.0f);
            float v = tanhf((sum + __ldg(&g_z[c])) * dc + b2v);
            sc[i] = v;
            x2c[i] = v;
        }
    }
    __syncthreads();

    // iterative stable top-K: max score, tie -> lowest index (matches lexsort)
    for (int j = 0; j < ksel; j++) {
        unsigned long long best = 0ull;
        for (int i = t; i < cnt; i += 256) {
            unsigned u = __float_as_uint(sc[i]);
            u = (u & 0x80000000u) ? ~u : (u | 0x80000000u);
            unsigned long long key =
                ((unsigned long long)u << 32) | (unsigned)(~i);
            if (key > best) best = key;
        }
#pragma unroll
        for (int off = 16; off; off >>= 1) {
            unsigned long long o2 = __shfl_xor_sync(~0u, best, off);
            best = max(best, o2);
        }
        if (lane == 0) redw[warp] = best;
        __syncthreads();
        if (warp == 0) {
            unsigned long long b2k = (lane < 8) ? redw[lane] : 0ull;
#pragma unroll
            for (int off = 4; off; off >>= 1) {
                unsigned long long o2 = __shfl_xor_sync(~0u, b2k, off);
                b2k = max(b2k, o2);
            }
            if (lane == 0) {
                int pos = (int)(~(unsigned)(b2k & 0xFFFFFFFFull));
                sel[j] = pos;
                sc[pos] = -CUDART_INF_F;
            }
        }
        __syncthreads();
    }

    for (int idx = t; idx < PLEN; idx += 256) {
        int j = idx / 65, c = idx % 65;
        float v = 0.f;
        if (j < ksel) {
            int pos = sel[j];
            v = (c < 64) ? g_x1[(size_t)(start + pos) * 64 + c] : x2c[pos];
        }
        p[idx] = v;
    }
    __syncthreads();

    for (int idx = t; idx < 320; idx += 256) {
        int oc = idx / 20, tt = idx % 20;
        float s = b3[oc];
        const float* w = w3 + oc * 97;
        const float* pp = p + tt * 97;
#pragma unroll 1
        for (int i = 0; i < 97; i++) s += pp[i] * w[i];
        c3[oc * 20 + tt] = fmaxf(s, 0.f);
    }
    __syncthreads();

    for (int idx = t; idx < 160; idx += 256) {
        int oc = idx / 10, tt = idx % 10;
        pl[idx] = fmaxf(c3[oc * 20 + 2 * tt], c3[oc * 20 + 2 * tt + 1]);
    }
    __syncthreads();

    for (int idx = t; idx < 192; idx += 256) {
        int oc = idx / 6, tt = idx % 6;
        float s = b4[oc];
#pragma unroll
        for (int ic = 0; ic < 16; ic++)
#pragma unroll
            for (int i = 0; i < 5; i++)
                s += pl[ic * 10 + tt + i] * w4[oc * 80 + ic * 5 + i];
        h[idx] = fmaxf(s, 0.f);
    }
    __syncthreads();

    for (int j = t; j < 128; j += 256) {
        float s = fb1[j];
#pragma unroll 4
        for (int i = 0; i < 192; i++) s += h[i] * fw1[i * 128 + j];
        float r = fmaxf(s, 0.f);
        ll[j] = r;
        out[(size_t)2 * B * 18 + (size_t)g * 128 + j] = r;
    }
    __syncthreads();

    for (int j = t; j < 18; j += 256) {
        float s = fb2[j];
#pragma unroll 4
        for (int i = 0; i < 128; i++) s += ll[i] * fw2[i * 18 + j];
        o[j] = s;
        out[(size_t)B * 18 + (size_t)g * 18 + j] = s;
    }
    __syncthreads();

    if (t == 0) {
        float m = o[0];
        for (int j = 1; j < 18; j++) m = fmaxf(m, o[j]);
        float se = 0.f;
        for (int j = 0; j < 18; j++) se += expf(o[j] - m);
        float lse = logf(se) + m;
        for (int j = 0; j < 18; j++) out[(size_t)g * 18 + j] = o[j] - lse;
    }
}

// ---------------- launch ----------------------------------------------------
extern "C" void kernel_launch(void* const* d_in, const int* in_sizes, int n_in,
                              void* d_out, int out_size) {
    const float* x    = (const float*)d_in[0];
    const int* ei     = (const int*)d_in[1];
    const int* batch  = (const int*)d_in[2];
    const float* W1   = (const float*)d_in[4];
    const float* b1   = (const float*)d_in[5];
    const float* W2   = (const float*)d_in[6];
    const float* b2   = (const float*)d_in[7];
    const float* w3   = (const float*)d_in[8];
    const float* b3   = (const float*)d_in[9];
    const float* w4   = (const float*)d_in[10];
    const float* b4   = (const float*)d_in[11];
    const float* fw1  = (const float*)d_in[12];
    const float* fb1  = (const float*)d_in[13];
    const float* fw2  = (const float*)d_in[14];
    const float* fb2  = (const float*)d_in[15];
    float* out = (float*)d_out;

    int n = in_sizes[0] / 128;
    int E = in_sizes[1] / 2;
    int B = out_size / 164;   // 18 + 18 + 128
    const int* row = ei;
    const int* col = ei + E;
    int EG8 = (E + 7) / 8;
    int nb = (n + SCAN_B - 1) / SCAN_B;   // scan blocks (<= NBLK)

    // lazy side-stream/event setup (host-side resources only)
    static cudaStream_t s2 = nullptr;
    static cudaEvent_t evFork = nullptr, evJoin = nullptr;
    if (!s2) {
        cudaStreamCreateWithFlags(&s2, cudaStreamNonBlocking);
        cudaEventCreateWithFlags(&evFork, cudaEventDisableTiming);
        cudaEventCreateWithFlags(&evJoin, cudaEventDisableTiming);
    }

    int n4 = (n + 3) / 4;
    zero_kernel<<<(n4 + 255) / 256, 256>>>(n4);
    deg_kernel<<<(EG8 + 255) / 256, 256>>>(row, col, E);

    // fork: side stream runs scanA -> scanC -> scatter
    cudaEventRecord(evFork, 0);
    cudaStreamWaitEvent(s2, evFork, 0);
    scanA_kernel<<<nb, SCAN_B, 0, s2>>>(n);
    scanC_kernel<<<(n + 255) / 256, 256, 0, s2>>>(n, nb);
    scatter_kernel<<<(EG8 + 255) / 256, 256, 0, s2>>>(row, col, E);
    cudaEventRecord(evJoin, s2);

    // main stream runs gemm concurrently
    cudaFuncSetAttribute(gemm1_kernel,
                         cudaFuncAttributeMaxDynamicSharedMemorySize, GEMM_SMEM);
    gemm1_kernel<<<(n + GEMM_TR - 1) / GEMM_TR, 256, GEMM_SMEM>>>(x, W1, n);

    // join: gather1 needs both gemm (g_y) and scatter (g_srow/g_estart)
    cudaStreamWaitEvent(0, evJoin, 0);

    gather1_kernel<<<(n * 32 + 255) / 256, 256>>>(W2, b1, n);

    head_kernel<<<B, 256>>>(batch, b2, w3, b3, w4, b4,
                            fw1, fb1, fw2, fb2, out, B, n);
}

// round 16
// speedup vs baseline: 1.0364x; 1.0364x over previous
#include <cuda_runtime.h>
#include <cstdint>
#include <math_constants.h>

#define NMAX 100000
#define EMAX 3200000
#define CH 64
#define KTOP 30
#define PLEN 1950   // 30 * 65
#define SEGMAX 4096
#define SCAN_B 1024
#define NBLK 128    // >= ceil(NMAX/SCAN_B) = 98

#define FMA_F32X2(d, a, b, c) \
    asm("fma.rn.f32x2 %0, %1, %2, %3;" : "=l"(d) : "l"(a), "l"(b), "l"(c))
#define PACK_DUP_F32X2(d, a) \
    asm("mov.b64 %0, {%1, %1};" : "=l"(d) : "f"(a))
#define UNPACK_F32X2(lo, hi, in) \
    asm("mov.b64 {%0, %1}, %2;" : "=f"(lo), "=f"(hi) : "l"(in))

// ---------------- scratch (static device globals; no allocs allowed) -------
// g_indeg is zero at module load and re-zeroed by head_kernel at the end of
// every invocation, so deg_kernel always sees zeros (graph-replay safe).
__device__ float g_y[NMAX * CH];     // (x @ W1) * dis[row]
__device__ float g_x1[NMAX * CH];
__device__ float g_z[NMAX];          // (x1 @ W2) * dis[row]
__device__ float g_x2[NMAX];
__device__ int   g_indeg[NMAX];
__device__ int   g_lpre[NMAX];       // exclusive prefix within scan block
__device__ int   g_bsum[NBLK];
__device__ int   g_estart[NMAX + 1];
__device__ int   g_cursor[NMAX];
__device__ int   g_srow[EMAX];       // edge sources grouped by destination

// ---------------- K1: in-degree counts (8-edge batched, int) ----------------
__global__ void deg_kernel(const int* __restrict__ row,
                           const int* __restrict__ col, int E) {
    int g = blockIdx.x * blockDim.x + threadIdx.x;
    int e0 = g * 8;
    if (e0 >= E) return;
    int rr[8], cc[8];
    if (e0 + 7 < E) {
        int4 r0 = __ldg((const int4*)row + g * 2);
        int4 r1 = __ldg((const int4*)row + g * 2 + 1);
        int4 c0 = __ldg((const int4*)col + g * 2);
        int4 c1 = __ldg((const int4*)col + g * 2 + 1);
        rr[0]=r0.x; rr[1]=r0.y; rr[2]=r0.z; rr[3]=r0.w;
        rr[4]=r1.x; rr[5]=r1.y; rr[6]=r1.z; rr[7]=r1.w;
        cc[0]=c0.x; cc[1]=c0.y; cc[2]=c0.z; cc[3]=c0.w;
        cc[4]=c1.x; cc[5]=c1.y; cc[6]=c1.z; cc[7]=c1.w;
    } else {
#pragma unroll
        for (int k = 0; k < 8; k++) {
            int e = e0 + k;
            rr[k] = (e < E) ? row[e] : 0;
            cc[k] = (e < E) ? col[e] : 0;
        }
    }
#pragma unroll
    for (int k = 0; k < 8; k++)
        if (rr[k] != cc[k]) atomicAdd(&g_indeg[cc[k]], 1);
}

// ---------------- K2a: per-block scan of indeg ------------------------------
__global__ void scanA_kernel(int n) {
    __shared__ int s[SCAN_B];
    int b = blockIdx.x, t = threadIdx.x;
    int i = b * SCAN_B + t;
    int v = (i < n) ? g_indeg[i] : 0;
    s[t] = v;
    __syncthreads();
    for (int off = 1; off < SCAN_B; off <<= 1) {
        int u = (t >= off) ? s[t - off] : 0;
        __syncthreads();
        s[t] += u;
        __syncthreads();
    }
    if (i < n) g_lpre[i] = s[t] - v;
    if (t == SCAN_B - 1) g_bsum[b] = s[t];
}

// ---------------- K2c: scan block sums locally; apply -> estart, cursor -----
__global__ void scanC_kernel(int n, int nb) {
    __shared__ int bs[NBLK];
    int t = threadIdx.x;
    if (t < NBLK) bs[t] = (t < nb) ? g_bsum[t] : 0;
    __syncthreads();
    for (int off = 1; off < NBLK; off <<= 1) {
        int u = (t >= off && t < NBLK) ? bs[t - off] : 0;
        __syncthreads();
        if (t < NBLK) bs[t] += u;   // inclusive scan of block sums
        __syncthreads();
    }
    int i = blockIdx.x * blockDim.x + t;
    if (i < n) {
        int b = i >> 10;
        int pre = b ? bs[b - 1] : 0;
        int v = g_lpre[i] + pre;
        g_estart[i] = v;
        g_cursor[i] = v;
    }
    if (blockIdx.x == 0 && t == 0)
        g_estart[n] = bs[nb - 1];   // total non-self edges
}

// ---------------- K3: y = (x @ W1) * rsqrt(indeg+1) -------------------------
#define GEMM_TR 128
#define XPITCH 132
#define GEMM_SMEM ((GEMM_TR * XPITCH + 128 * 64) * 4)

__global__ void gemm1_kernel(const float* __restrict__ x,
                             const float* __restrict__ W, int n) {
    extern __shared__ float smem[];
    float* xs = smem;                       // [128][132]
    float* ws = smem + GEMM_TR * XPITCH;    // [128][64]
    int t = threadIdx.x;
    int row0 = blockIdx.x * GEMM_TR;

    for (int i = t; i < 128 * 64 / 4; i += 256)
        ((float4*)ws)[i] = ((const float4*)W)[i];
    for (int i = t; i < GEMM_TR * 32; i += 256) {
        int r = i >> 5, c4 = i & 31;
        float4 v = make_float4(0.f, 0.f, 0.f, 0.f);
        if (row0 + r < n) v = ((const float4*)x)[(size_t)(row0 + r) * 32 + c4];
        *(float4*)&xs[r * XPITCH + c4 * 4] = v;
    }
    __syncthreads();

    int tx = t & 7;
    int ty = t >> 3;
    unsigned long long acc[4][4];
#pragma unroll
    for (int i = 0; i < 4; i++)
#pragma unroll
        for (int j = 0; j < 4; j++) acc[i][j] = 0ull;

#pragma unroll 4
    for (int k = 0; k < 128; k++) {
        const unsigned long long* w64 =
            (const unsigned long long*)(ws + k * 64 + tx * 8);
        unsigned long long b0 = w64[0], b1 = w64[1], b2 = w64[2], b3 = w64[3];
#pragma unroll
        for (int i = 0; i < 4; i++) {
            float a = xs[(ty * 4 + i) * XPITCH + k];
            unsigned long long ad;
            PACK_DUP_F32X2(ad, a);
            FMA_F32X2(acc[i][0], ad, b0, acc[i][0]);
            FMA_F32X2(acc[i][1], ad, b1, acc[i][1]);
            FMA_F32X2(acc[i][2], ad, b2, acc[i][2]);
            FMA_F32X2(acc[i][3], ad, b3, acc[i][3]);
        }
    }

#pragma unroll
    for (int i = 0; i < 4; i++) {
        int r = row0 + ty * 4 + i;
        if (r < n) {
            float d = rsqrtf((float)g_indeg[r] + 1.0f);
            float f[8];
#pragma unroll
            for (int j = 0; j < 4; j++)
                UNPACK_F32X2(f[2 * j], f[2 * j + 1], acc[i][j]);
            size_t ofs = (size_t)r * 64 + tx * 8;
            *(float4*)&g_y[ofs] =
                make_float4(f[0] * d, f[1] * d, f[2] * d, f[3] * d);
            *(float4*)&g_y[ofs + 4] =
                make_float4(f[4] * d, f[5] * d, f[6] * d, f[7] * d);
        }
    }
}

// ---------------- K4: scatter edges into dest-grouped list (8-batched) ------
__global__ void scatter_kernel(const int* __restrict__ row,
                               const int* __restrict__ col, int E) {
    int g = blockIdx.x * blockDim.x + threadIdx.x;
    int e0 = g * 8;
    if (e0 >= E) return;
    int rr[8], cc[8];
    if (e0 + 7 < E) {
        int4 r0 = __ldg((const int4*)row + g * 2);
        int4 r1 = __ldg((const int4*)row + g * 2 + 1);
        int4 c0 = __ldg((const int4*)col + g * 2);
        int4 c1 = __ldg((const int4*)col + g * 2 + 1);
        rr[0]=r0.x; rr[1]=r0.y; rr[2]=r0.z; rr[3]=r0.w;
        rr[4]=r1.x; rr[5]=r1.y; rr[6]=r1.z; rr[7]=r1.w;
        cc[0]=c0.x; cc[1]=c0.y; cc[2]=c0.z; cc[3]=c0.w;
        cc[4]=c1.x; cc[5]=c1.y; cc[6]=c1.z; cc[7]=c1.w;
    } else {
#pragma unroll
        for (int k = 0; k < 8; k++) {
            int e = e0 + k;
            rr[k] = (e < E) ? row[e] : 0;
            cc[k] = (e < E) ? col[e] : 0;
        }
    }
    int pos[8];
#pragma unroll
    for (int k = 0; k < 8; k++)
        if (rr[k] != cc[k]) pos[k] = atomicAdd(&g_cursor[cc[k]], 1);
#pragma unroll
    for (int k = 0; k < 8; k++)
        if (rr[k] != cc[k]) g_srow[pos[k]] = rr[k];
}

// ---------------- K5: gather conv1 + tanh + W2 dot (warp/node, unroll-4) ----
__global__ void gather1_kernel(const float* __restrict__ W2,
                               const float* __restrict__ b1, int n) {
    int c = (blockIdx.x * blockDim.x + threadIdx.x) >> 5;
    int lane = threadIdx.x & 31;
    if (c >= n) return;
    int s = __ldg(&g_estart[c]);
    int e = __ldg(&g_estart[c + 1]);

    size_t base = (size_t)c * 64 + lane * 2;
    float2 self = *(const float2*)&g_y[base];
    float2 a0 = make_float2(0.f, 0.f), a1 = a0, a2 = a0, a3 = a0;

    int i = s;
    for (; i + 4 <= e; i += 4) {
        int r0 = __ldg(&g_srow[i]);
        int r1 = __ldg(&g_srow[i + 1]);
        int r2 = __ldg(&g_srow[i + 2]);
        int r3 = __ldg(&g_srow[i + 3]);
        float2 v0 = *(const float2*)&g_y[(size_t)r0 * 64 + lane * 2];
        float2 v1 = *(const float2*)&g_y[(size_t)r1 * 64 + lane * 2];
        float2 v2 = *(const float2*)&g_y[(size_t)r2 * 64 + lane * 2];
        float2 v3 = *(const float2*)&g_y[(size_t)r3 * 64 + lane * 2];
        a0.x += v0.x; a0.y += v0.y;
        a1.x += v1.x; a1.y += v1.y;
        a2.x += v2.x; a2.y += v2.y;
        a3.x += v3.x; a3.y += v3.y;
    }
    for (; i < e; i++) {
        int r = __ldg(&g_srow[i]);
        float2 v = *(const float2*)&g_y[(size_t)r * 64 + lane * 2];
        a0.x += v.x; a0.y += v.y;
    }
    float accx = (a0.x + a1.x) + (a2.x + a3.x) + self.x;
    float accy = (a0.y + a1.y) + (a2.y + a3.y) + self.y;

    float dc = rsqrtf((float)g_indeg[c] + 1.0f);
    float2 bb = *(const float2*)&b1[lane * 2];
    float v0 = tanhf(accx * dc + bb.x);
    float v1 = tanhf(accy * dc + bb.y);
    *(float2*)&g_x1[base] = make_float2(v0, v1);

    float2 w2 = *(const float2*)&W2[lane * 2];
    float dot = v0 * w2.x + v1 * w2.y;
#pragma unroll
    for (int off = 16; off; off >>= 1) dot += __shfl_xor_sync(~0u, dot, off);
    if (lane == 0) g_z[c] = dot * dc;
}

// ---------------- K6: gather conv2 + x2 (warp per node) ----------------------
__global__ void gather2_kernel(const float* __restrict__ b2, int n) {
    int c = (blockIdx.x * blockDim.x + threadIdx.x) >> 5;
    int lane = threadIdx.x & 31;
    if (c >= n) return;
    int s = __ldg(&g_estart[c]);
    int e = __ldg(&g_estart[c + 1]);
    float sum = 0.f;
    for (int i = s + lane; i < e; i += 32) {
        int r = __ldg(&g_srow[i]);
        sum += __ldg(&g_z[r]);
    }
#pragma unroll
    for (int off = 16; off; off >>= 1) sum += __shfl_xor_sync(~0u, sum, off);
    if (lane == 0) {
        float dc = rsqrtf((float)g_indeg[c] + 1.0f);
        g_x2[c] = tanhf((sum + g_z[c]) * dc + b2[0]);
    }
}

// ---------------- K9: sort-pool(top-30) + CNN head + MLP + logsoftmax -------
// Also re-zeroes g_indeg for the next invocation (all indeg readers are
// earlier in the stream; device globals start zeroed at module load).
__device__ __forceinline__ int lower_bound_i(const int* __restrict__ b,
                                             int n, int v) {
    int lo = 0, hi = n;
    while (lo < hi) {
        int m = (lo + hi) >> 1;
        if (__ldg(b + m) < v) lo = m + 1; else hi = m;
    }
    return lo;
}

__global__ void head_kernel(const int* __restrict__ batch,
                            const float* __restrict__ w3, const float* __restrict__ b3,
                            const float* __restrict__ w4, const float* __restrict__ b4,
                            const float* __restrict__ fw1, const float* __restrict__ fb1,
                            const float* __restrict__ fw2, const float* __restrict__ fb2,
                            float* __restrict__ out, int B, int n) {
    __shared__ float sc[SEGMAX];    // selection scores (destroyed)
    __shared__ float x2c[SEGMAX];   // preserved x2 copy
    __shared__ int sel[KTOP];
    __shared__ float p[PLEN];
    __shared__ float c3[320];
    __shared__ float pl[160];
    __shared__ float h[192];
    __shared__ float ll[128];
    __shared__ float o[18];
    __shared__ unsigned long long redw[8];

    int g = blockIdx.x;
    int t = threadIdx.x;
    int lane = t & 31;
    int warp = t >> 5;

    // zero indeg for next invocation (grid covers n: B*256 >= n)
    int zid = g * 256 + t;
    if (zid < n) g_indeg[zid] = 0;

    int start = lower_bound_i(batch, n, g);
    int end   = lower_bound_i(batch, n, g + 1);
    int cnt = min(end - start, SEGMAX);
    int ksel = min(cnt, KTOP);

    for (int i = t; i < cnt; i += 256) {
        float v = g_x2[start + i];
        sc[i] = v;
        x2c[i] = v;
    }
    __syncthreads();

    // iterative stable top-K: max score, tie -> lowest index (matches lexsort)
    for (int j = 0; j < ksel; j++) {
        unsigned long long best = 0ull;
        for (int i = t; i < cnt; i += 256) {
            unsigned u = __float_as_uint(sc[i]);
            u = (u & 0x80000000u) ? ~u : (u | 0x80000000u);
            unsigned long long key =
                ((unsigned long long)u << 32) | (unsigned)(~i);
            if (key > best) best = key;
        }
#pragma unroll
        for (int off = 16; off; off >>= 1) {
            unsigned long long o2 = __shfl_xor_sync(~0u, best, off);
            best = max(best, o2);
        }
        if (lane == 0) redw[warp] = best;
        __syncthreads();
        if (warp == 0) {
            unsigned long long b2k = (lane < 8) ? redw[lane] : 0ull;
#pragma unroll
            for (int off = 4; off; off >>= 1) {
                unsigned long long o2 = __shfl_xor_sync(~0u, b2k, off);
                b2k = max(b2k, o2);
            }
            if (lane == 0) {
                int pos = (int)(~(unsigned)(b2k & 0xFFFFFFFFull));
                sel[j] = pos;
                sc[pos] = -CUDART_INF_F;
            }
        }
        __syncthreads();
    }

    for (int idx = t; idx < PLEN; idx += 256) {
        int j = idx / 65, c = idx % 65;
        float v = 0.f;
        if (j < ksel) {
            int pos = sel[j];
            v = (c < 64) ? g_x1[(size_t)(start + pos) * 64 + c] : x2c[pos];
        }
        p[idx] = v;
    }
    __syncthreads();

    for (int idx = t; idx < 320; idx += 256) {
        int oc = idx / 20, tt = idx % 20;
        float s = b3[oc];
        const float* w = w3 + oc * 97;
        const float* pp = p + tt * 97;
#pragma unroll 1
        for (int i = 0; i < 97; i++) s += pp[i] * w[i];
        c3[oc * 20 + tt] = fmaxf(s, 0.f);
    }
    __syncthreads();

    for (int idx = t; idx < 160; idx += 256) {
        int oc = idx / 10, tt = idx % 10;
        pl[idx] = fmaxf(c3[oc * 20 + 2 * tt], c3[oc * 20 + 2 * tt + 1]);
    }
    __syncthreads();

    for (int idx = t; idx < 192; idx += 256) {
        int oc = idx / 6, tt = idx % 6;
        float s = b4[oc];
#pragma unroll
        for (int ic = 0; ic < 16; ic++)
#pragma unroll
            for (int i = 0; i < 5; i++)
                s += pl[ic * 10 + tt + i] * w4[oc * 80 + ic * 5 + i];
        h[idx] = fmaxf(s, 0.f);
    }
    __syncthreads();

    for (int j = t; j < 128; j += 256) {
        float s = fb1[j];
#pragma unroll 4
        for (int i = 0; i < 192; i++) s += h[i] * fw1[i * 128 + j];
        float r = fmaxf(s, 0.f);
        ll[j] = r;
        out[(size_t)2 * B * 18 + (size_t)g * 128 + j] = r;
    }
    __syncthreads();

    for (int j = t; j < 18; j += 256) {
        float s = fb2[j];
#pragma unroll 4
        for (int i = 0; i < 128; i++) s += ll[i] * fw2[i * 18 + j];
        o[j] = s;
        out[(size_t)B * 18 + (size_t)g * 18 + j] = s;
    }
    __syncthreads();

    if (t == 0) {
        float m = o[0];
        for (int j = 1; j < 18; j++) m = fmaxf(m, o[j]);
        float se = 0.f;
        for (int j = 0; j < 18; j++) se += expf(o[j] - m);
        float lse = logf(se) + m;
        for (int j = 0; j < 18; j++) out[(size_t)g * 18 + j] = o[j] - lse;
    }
}

// ---------------- launch ----------------------------------------------------
extern "C" void kernel_launch(void* const* d_in, const int* in_sizes, int n_in,
                              void* d_out, int out_size) {
    const float* x    = (const float*)d_in[0];
    const int* ei     = (const int*)d_in[1];
    const int* batch  = (const int*)d_in[2];
    const float* W1   = (const float*)d_in[4];
    const float* b1   = (const float*)d_in[5];
    const float* W2   = (const float*)d_in[6];
    const float* b2   = (const float*)d_in[7];
    const float* w3   = (const float*)d_in[8];
    const float* b3   = (const float*)d_in[9];
    const float* w4   = (const float*)d_in[10];
    const float* b4   = (const float*)d_in[11];
    const float* fw1  = (const float*)d_in[12];
    const float* fb1  = (const float*)d_in[13];
    const float* fw2  = (const float*)d_in[14];
    const float* fb2  = (const float*)d_in[15];
    float* out = (float*)d_out;

    int n = in_sizes[0] / 128;
    int E = in_sizes[1] / 2;
    int B = out_size / 164;   // 18 + 18 + 128
    const int* row = ei;
    const int* col = ei + E;
    int EG8 = (E + 7) / 8;
    int nb = (n + SCAN_B - 1) / SCAN_B;   // scan blocks (<= NBLK)

    // lazy side-stream/event setup (host-side resources only)
    static cudaStream_t s2 = nullptr;
    static cudaEvent_t evFork = nullptr, evJoin = nullptr;
    if (!s2) {
        cudaStreamCreateWithFlags(&s2, cudaStreamNonBlocking);
        cudaEventCreateWithFlags(&evFork, cudaEventDisableTiming);
        cudaEventCreateWithFlags(&evJoin, cudaEventDisableTiming);
    }

    // g_indeg is zeroed by the previous invocation's head_kernel (or module
    // load on the very first call) — no explicit memset on the critical path.
    deg_kernel<<<(EG8 + 255) / 256, 256>>>(row, col, E);

    // fork: side stream runs scanA -> scanC -> scatter
    cudaEventRecord(evFork, 0);
    cudaStreamWaitEvent(s2, evFork, 0);
    scanA_kernel<<<nb, SCAN_B, 0, s2>>>(n);
    scanC_kernel<<<(n + 255) / 256, 256, 0, s2>>>(n, nb);
    scatter_kernel<<<(EG8 + 255) / 256, 256, 0, s2>>>(row, col, E);
    cudaEventRecord(evJoin, s2);

    // main stream runs gemm concurrently
    cudaFuncSetAttribute(gemm1_kernel,
                         cudaFuncAttributeMaxDynamicSharedMemorySize, GEMM_SMEM);
    gemm1_kernel<<<(n + GEMM_TR - 1) / GEMM_TR, 256, GEMM_SMEM>>>(x, W1, n);

    // join: gather1 needs both gemm (g_y) and scatter (g_srow/g_estart)
    cudaStreamWaitEvent(0, evJoin, 0);

    gather1_kernel<<<(n * 32 + 255) / 256, 256>>>(W2, b1, n);
    gather2_kernel<<<(n * 32 + 255) / 256, 256>>>(b2, n);

    head_kernel<<<B, 256>>>(batch, w3, b3, w4, b4,
                            fw1, fb1, fw2, fb2, out, B, n);
}